// round 1
// baseline (speedup 1.0000x reference)
#include <cuda_runtime.h>

#define NMAX 200000
#define KOFF 27
#define BN_EPS 1e-3f

// -------- scratch (no allocs allowed; __device__ globals) --------
__device__ __align__(256) float g_acc1[(size_t)NMAX * 32];
__device__ __align__(256) float g_x1  [(size_t)NMAX * 32];
__device__ __align__(256) float g_acc2[(size_t)NMAX * 32];
__device__ int   g_m[KOFF];
// [0:64)  layer1 sum/sumsq   [64:128) layer2 sum/sumsq
// [128:192) layer1 scale/shift  [192:256) layer2 scale/shift
__device__ float g_sums[256];

// -------- prep: count valid prefix per offset, zero stats --------
__global__ void prep_k(const int* __restrict__ rout, int n) {
    int k = blockIdx.x;
    int cnt = 0;
    for (int i = threadIdx.x; i < n; i += blockDim.x)
        cnt += (rout[(size_t)k * n + i] != n);
    __shared__ int sh[256];
    sh[threadIdx.x] = cnt;
    __syncthreads();
    for (int s = 128; s > 0; s >>= 1) {
        if (threadIdx.x < s) sh[threadIdx.x] += sh[threadIdx.x + s];
        __syncthreads();
    }
    if (threadIdx.x == 0) g_m[k] = sh[0];
    if (k == 0 && threadIdx.x < 128) g_sums[threadIdx.x] = 0.f;
}

// -------- conv: gather -> tile GEMM -> atomic scatter ------------
// grid = (ceil(n/128), 27), block = 256
// thread tile: 4 rows x 4 cols of the 128x32 C tile
template <int CIN>
__global__ void __launch_bounds__(256) conv_k(
    const float* __restrict__ feats, const float* __restrict__ W,
    const int* __restrict__ rin, const int* __restrict__ rout,
    float* __restrict__ acc, int n)
{
    const int AS = CIN + 1;                // smem row stride (conflict-free)
    int k  = blockIdx.y;
    int t0 = blockIdx.x * 128;
    if (t0 >= g_m[k]) return;              // pure-padding tile: skip

    __shared__ float Wsh[CIN * 32];
    __shared__ float Ash[128 * (CIN + 1)];
    __shared__ int   dsh[128];

    int tx = threadIdx.x;
    const float* Wk = W + (size_t)k * CIN * 32;
    #pragma unroll
    for (int i = tx; i < CIN * 32; i += 256) Wsh[i] = Wk[i];

    const int CH = CIN / 4;                // float4 chunks per row
    for (int i = tx; i < 128 * CH; i += 256) {
        int row = i / CH, co = i % CH;
        int p = t0 + row;
        float4 v = make_float4(0.f, 0.f, 0.f, 0.f);
        if (p < n) {
            int s = rin[(size_t)k * n + p];
            v = ((const float4*)(feats + (size_t)s * CIN))[co];
        }
        float* d = &Ash[row * AS + co * 4];
        d[0] = v.x; d[1] = v.y; d[2] = v.z; d[3] = v.w;
    }
    for (int i = tx; i < 128; i += 256) {
        int p = t0 + i;
        dsh[i] = (p < n) ? rout[(size_t)k * n + p] : n;
    }
    __syncthreads();

    int cg = tx & 7;       // column group: cols 4*cg..4*cg+3
    int rg = tx >> 3;      // row group:    rows 4*rg..4*rg+3
    float accv[4][4];
    #pragma unroll
    for (int r = 0; r < 4; r++)
        #pragma unroll
        for (int c = 0; c < 4; c++) accv[r][c] = 0.f;

    #pragma unroll
    for (int ci = 0; ci < CIN; ci++) {
        float4 w = *(const float4*)&Wsh[ci * 32 + cg * 4];
        float a0 = Ash[(4 * rg + 0) * AS + ci];
        float a1 = Ash[(4 * rg + 1) * AS + ci];
        float a2 = Ash[(4 * rg + 2) * AS + ci];
        float a3 = Ash[(4 * rg + 3) * AS + ci];
        accv[0][0] = fmaf(a0, w.x, accv[0][0]);
        accv[0][1] = fmaf(a0, w.y, accv[0][1]);
        accv[0][2] = fmaf(a0, w.z, accv[0][2]);
        accv[0][3] = fmaf(a0, w.w, accv[0][3]);
        accv[1][0] = fmaf(a1, w.x, accv[1][0]);
        accv[1][1] = fmaf(a1, w.y, accv[1][1]);
        accv[1][2] = fmaf(a1, w.z, accv[1][2]);
        accv[1][3] = fmaf(a1, w.w, accv[1][3]);
        accv[2][0] = fmaf(a2, w.x, accv[2][0]);
        accv[2][1] = fmaf(a2, w.y, accv[2][1]);
        accv[2][2] = fmaf(a2, w.z, accv[2][2]);
        accv[2][3] = fmaf(a2, w.w, accv[2][3]);
        accv[3][0] = fmaf(a3, w.x, accv[3][0]);
        accv[3][1] = fmaf(a3, w.y, accv[3][1]);
        accv[3][2] = fmaf(a3, w.z, accv[3][2]);
        accv[3][3] = fmaf(a3, w.w, accv[3][3]);
    }

    #pragma unroll
    for (int r = 0; r < 4; r++) {
        int d = dsh[4 * rg + r];
        if (d < n) {                       // skip padding sink
            float* p = acc + (size_t)d * 32 + cg * 4;
            atomicAdd(p + 0, accv[r][0]);
            atomicAdd(p + 1, accv[r][1]);
            atomicAdd(p + 2, accv[r][2]);
            atomicAdd(p + 3, accv[r][3]);
        }
    }
}

// -------- BN stats: per-channel sum & sumsq ----------------------
__global__ void stats_k(const float* __restrict__ x, int n, int off) {
    int lane = threadIdx.x & 31, wid = threadIdx.x >> 5;
    float s = 0.f, q = 0.f;
    for (int r = blockIdx.x * 8 + wid; r < n; r += gridDim.x * 8) {
        float v = x[(size_t)r * 32 + lane];
        s += v;
        q = fmaf(v, v, q);
    }
    __shared__ float sh[16][32];
    sh[wid][lane] = s;
    sh[wid + 8][lane] = q;
    __syncthreads();
    if (wid == 0) {
        float S = 0.f, Q = 0.f;
        #pragma unroll
        for (int w = 0; w < 8; w++) { S += sh[w][lane]; Q += sh[w + 8][lane]; }
        atomicAdd(&g_sums[off + lane], S);
        atomicAdd(&g_sums[off + 32 + lane], Q);
    }
}

// -------- BN finalize: scale/shift per channel -------------------
__global__ void finalize_k(const float* __restrict__ gamma,
                           const float* __restrict__ beta,
                           int n, int off, int outoff) {
    int c = threadIdx.x;
    float inv_n = 1.f / (float)n;
    float mu  = g_sums[off + c] * inv_n;
    float var = g_sums[off + 32 + c] * inv_n - mu * mu;
    float sc  = gamma[c] * rsqrtf(var + BN_EPS);
    g_sums[outoff + c] = sc;
    g_sums[outoff + 32 + c] = beta[c] - mu * sc;
}

// -------- BN apply + ReLU (float4) -------------------------------
__global__ void apply_k(const float* __restrict__ in, float* __restrict__ out,
                        int n, int soff) {
    int total = n * 8;                     // float4 elements
    for (int i = blockIdx.x * blockDim.x + threadIdx.x; i < total;
         i += gridDim.x * blockDim.x) {
        int c4 = (i & 7) * 4;
        float4 v  = ((const float4*)in)[i];
        float4 sc = *(const float4*)&g_sums[soff + c4];
        float4 sh = *(const float4*)&g_sums[soff + 32 + c4];
        float4 o;
        o.x = fmaxf(fmaf(v.x, sc.x, sh.x), 0.f);
        o.y = fmaxf(fmaf(v.y, sc.y, sh.y), 0.f);
        o.z = fmaxf(fmaf(v.z, sc.z, sh.z), 0.f);
        o.w = fmaxf(fmaf(v.w, sc.w, sh.w), 0.f);
        ((float4*)out)[i] = o;
    }
}

// -------- launch --------------------------------------------------
extern "C" void kernel_launch(void* const* d_in, const int* in_sizes, int n_in,
                              void* d_out, int out_size) {
    const float* feats  = (const float*)d_in[0];
    const float* W1     = (const float*)d_in[1];
    const float* gamma1 = (const float*)d_in[2];
    const float* beta1  = (const float*)d_in[3];
    const float* W2     = (const float*)d_in[4];
    const float* gamma2 = (const float*)d_in[5];
    const float* beta2  = (const float*)d_in[6];
    const int*   rin    = (const int*)d_in[7];
    const int*   rout   = (const int*)d_in[8];
    int n = in_sizes[0] / 16;

    float *acc1, *x1, *acc2;
    cudaGetSymbolAddress((void**)&acc1, g_acc1);
    cudaGetSymbolAddress((void**)&x1,   g_x1);
    cudaGetSymbolAddress((void**)&acc2, g_acc2);

    int tiles = (n + 127) / 128;

    prep_k<<<KOFF, 256>>>(rout, n);

    cudaMemsetAsync(acc1, 0, (size_t)n * 32 * sizeof(float));
    conv_k<16><<<dim3(tiles, KOFF), 256>>>(feats, W1, rin, rout, acc1, n);
    stats_k<<<592, 256>>>(acc1, n, 0);
    finalize_k<<<1, 32>>>(gamma1, beta1, n, 0, 128);
    apply_k<<<1184, 256>>>(acc1, x1, n, 128);

    cudaMemsetAsync(acc2, 0, (size_t)n * 32 * sizeof(float));
    conv_k<32><<<dim3(tiles, KOFF), 256>>>(x1, W2, rin, rout, acc2, n);
    stats_k<<<592, 256>>>(acc2, n, 64);
    finalize_k<<<1, 32>>>(gamma2, beta2, n, 64, 192);
    apply_k<<<1184, 256>>>(acc2, (float*)d_out, n, 192);
}

// round 2
// speedup vs baseline: 1.9881x; 1.9881x over previous
#include <cuda_runtime.h>

#define NMAX 200000
#define KOFF 27
#define TILE 128
#define TILESMAX ((NMAX + TILE - 1) / TILE)
#define SEGW (TILESMAX + 1)
#define BN_EPS 1e-3f

// ---------------- scratch (__device__ globals; no allocs allowed) ----------
__device__ __align__(256) float g_acc1[(size_t)NMAX * 32];
__device__ __align__(256) float g_acc2[(size_t)NMAX * 32];
__device__ int   g_seg[KOFF * SEGW];
// [0:64) layer1 sum/sumsq  [64:128) layer2 sum/sumsq
// [128:192) layer1 scale/shift  [192:256) layer2 scale/shift
__device__ float g_sums[256];

// ---------------- seg: per (k, dst-tile) pair-range via binary search ------
// rule_out[k] is sorted ascending (padding value n at the tail).
__global__ void seg_k(const int* __restrict__ rout, int n, int tiles) {
    if (blockIdx.x == 0 && threadIdx.x < 128) g_sums[threadIdx.x] = 0.f;
    int idx = blockIdx.x * blockDim.x + threadIdx.x;
    int total = KOFF * (tiles + 1);
    if (idx >= total) return;
    int k = idx / (tiles + 1), t = idx % (tiles + 1);
    int target = t * TILE;
    if (target > n) target = n;           // clamp: padding rows hold value n
    const int* a = rout + (size_t)k * n;
    int lo = 0, hi = n;
    while (lo < hi) {
        int mid = (lo + hi) >> 1;
        if (a[mid] < target) lo = mid + 1; else hi = mid;
    }
    g_seg[k * SEGW + t] = lo;
}

// ---------------- conv: dst-tile smem accumulation, no global atomics ------
// Block owns 128 output rows. For each offset k, pairs hitting this tile are
// the contiguous range [seg[k][t], seg[k][t+1]). Gather -> register-tile GEMM
// (warp-granular skip past L) -> smem C scatter-add -> single store + fused
// BN-stats reduction.
template <int CIN, bool BNIN>
__global__ void __launch_bounds__(256) conv_k(
    const float* __restrict__ X, const float* __restrict__ W,
    const int* __restrict__ rin, const int* __restrict__ rout,
    float* __restrict__ out, int n, int statoff)
{
    const int AS = CIN + 4;               // Ash row stride (bank spread, 16B-aligned)
    const int CH = CIN / 4;               // float4 chunks per feature row
    __shared__ float C[128 * 36];         // C tile, stride 36 floats
    __shared__ float Ash[128 * (CIN + 4)];
    __shared__ float Wsh[CIN * 32];
    __shared__ int   dsh[128];
    __shared__ float red[512];
    __shared__ float bns[64];             // input-BN scale/shift (conv2)

    int tx = threadIdx.x;
    int tile = blockIdx.x;
    int r0 = tile * TILE;

    if (BNIN && tx < 64) bns[tx] = g_sums[128 + tx];
    for (int i = tx; i < 128 * 36; i += 256) C[i] = 0.f;

    for (int k = 0; k < KOFF; k++) {
        int s = g_seg[k * SEGW + tile];
        int L = g_seg[k * SEGW + tile + 1] - s;
        __syncthreads();                  // Ash/Wsh reuse + C-zero visibility

        // stage W_k
        const float4* Wk4 = (const float4*)(W + (size_t)k * CIN * 32);
        for (int i = tx; i < CIN * 8; i += 256) ((float4*)Wsh)[i] = Wk4[i];

        if (L > 0) {
            if (tx < L) dsh[tx] = rout[(size_t)k * n + s + tx] - r0;
            for (int i = tx; i < L * CH; i += 256) {
                int row = i / CH, co = i % CH;
                int src = __ldg(rin + (size_t)k * n + s + row);
                float4 v = ((const float4*)(X + (size_t)src * CIN))[co];
                if (BNIN) {
                    float4 sc = *(const float4*)&bns[co * 4];
                    float4 sh = *(const float4*)&bns[32 + co * 4];
                    v.x = fmaxf(fmaf(v.x, sc.x, sh.x), 0.f);
                    v.y = fmaxf(fmaf(v.y, sc.y, sh.y), 0.f);
                    v.z = fmaxf(fmaf(v.z, sc.z, sh.z), 0.f);
                    v.w = fmaxf(fmaf(v.w, sc.w, sh.w), 0.f);
                }
                *(float4*)&Ash[row * AS + co * 4] = v;
            }
        }
        __syncthreads();
        if (L == 0) continue;

        int wbase = (tx >> 5) * 16;       // warp covers pair rows [wbase, wbase+16)
        if (wbase < L) {
            int rg = tx >> 3, cg = tx & 7;
            int rb = rg * 4;
            float4 cc[4];
            #pragma unroll
            for (int i = 0; i < 4; i++) cc[i] = make_float4(0.f, 0.f, 0.f, 0.f);
            #pragma unroll
            for (int ci = 0; ci < CIN; ci++) {
                float4 w4 = *(const float4*)&Wsh[ci * 32 + cg * 4];
                float a0 = Ash[(rb + 0) * AS + ci];
                float a1 = Ash[(rb + 1) * AS + ci];
                float a2 = Ash[(rb + 2) * AS + ci];
                float a3 = Ash[(rb + 3) * AS + ci];
                cc[0].x = fmaf(a0, w4.x, cc[0].x); cc[0].y = fmaf(a0, w4.y, cc[0].y);
                cc[0].z = fmaf(a0, w4.z, cc[0].z); cc[0].w = fmaf(a0, w4.w, cc[0].w);
                cc[1].x = fmaf(a1, w4.x, cc[1].x); cc[1].y = fmaf(a1, w4.y, cc[1].y);
                cc[1].z = fmaf(a1, w4.z, cc[1].z); cc[1].w = fmaf(a1, w4.w, cc[1].w);
                cc[2].x = fmaf(a2, w4.x, cc[2].x); cc[2].y = fmaf(a2, w4.y, cc[2].y);
                cc[2].z = fmaf(a2, w4.z, cc[2].z); cc[2].w = fmaf(a2, w4.w, cc[2].w);
                cc[3].x = fmaf(a3, w4.x, cc[3].x); cc[3].y = fmaf(a3, w4.y, cc[3].y);
                cc[3].z = fmaf(a3, w4.z, cc[3].z); cc[3].w = fmaf(a3, w4.w, cc[3].w);
            }
            #pragma unroll
            for (int i = 0; i < 4; i++) {
                int row = rb + i;
                if (row < L) {
                    // distinct (row -> dst, cg) per lane within an offset: race-free
                    float* p = &C[dsh[row] * 36 + cg * 4];
                    float4 cv = *(float4*)p;
                    cv.x += cc[i].x; cv.y += cc[i].y;
                    cv.z += cc[i].z; cv.w += cc[i].w;
                    *(float4*)p = cv;
                }
            }
        }
    }
    __syncthreads();

    // epilogue: store C tile once + fused BN statistics
    int nrows = n - r0; if (nrows > 128) nrows = 128;
    for (int i = tx; i < nrows * 8; i += 256) {
        int row = i >> 3, co = i & 7;
        ((float4*)(out + (size_t)(r0 + row) * 32))[co] = *(float4*)&C[row * 36 + co * 4];
    }
    int ch = tx & 31, rb2 = tx >> 5;
    float s = 0.f, q = 0.f;
    for (int r = rb2; r < nrows; r += 8) {
        float v = C[r * 36 + ch];
        s += v;
        q = fmaf(v, v, q);
    }
    red[tx] = s; red[256 + tx] = q;
    __syncthreads();
    if (tx < 32) {
        float S = 0.f, Q = 0.f;
        #pragma unroll
        for (int w = 0; w < 8; w++) { S += red[w * 32 + tx]; Q += red[256 + w * 32 + tx]; }
        atomicAdd(&g_sums[statoff + tx], S);
        atomicAdd(&g_sums[statoff + 32 + tx], Q);
    }
}

// ---------------- BN finalize: per-channel scale/shift ---------------------
__global__ void finalize_k(const float* __restrict__ gamma,
                           const float* __restrict__ beta,
                           int n, int off, int outoff) {
    int c = threadIdx.x;
    float inv_n = 1.f / (float)n;
    float mu  = g_sums[off + c] * inv_n;
    float var = g_sums[off + 32 + c] * inv_n - mu * mu;
    float sc  = gamma[c] * rsqrtf(var + BN_EPS);
    g_sums[outoff + c] = sc;
    g_sums[outoff + 32 + c] = beta[c] - mu * sc;
}

// ---------------- BN apply + ReLU (final output only) ----------------------
__global__ void apply_k(const float* __restrict__ in, float* __restrict__ out,
                        int n, int soff) {
    int total = n * 8;
    for (int i = blockIdx.x * blockDim.x + threadIdx.x; i < total;
         i += gridDim.x * blockDim.x) {
        int c4 = (i & 7) * 4;
        float4 v  = ((const float4*)in)[i];
        float4 sc = *(const float4*)&g_sums[soff + c4];
        float4 sh = *(const float4*)&g_sums[soff + 32 + c4];
        float4 o;
        o.x = fmaxf(fmaf(v.x, sc.x, sh.x), 0.f);
        o.y = fmaxf(fmaf(v.y, sc.y, sh.y), 0.f);
        o.z = fmaxf(fmaf(v.z, sc.z, sh.z), 0.f);
        o.w = fmaxf(fmaf(v.w, sc.w, sh.w), 0.f);
        ((float4*)out)[i] = o;
    }
}

// ---------------- launch ---------------------------------------------------
extern "C" void kernel_launch(void* const* d_in, const int* in_sizes, int n_in,
                              void* d_out, int out_size) {
    const float* feats  = (const float*)d_in[0];
    const float* W1     = (const float*)d_in[1];
    const float* gamma1 = (const float*)d_in[2];
    const float* beta1  = (const float*)d_in[3];
    const float* W2     = (const float*)d_in[4];
    const float* gamma2 = (const float*)d_in[5];
    const float* beta2  = (const float*)d_in[6];
    const int*   rin    = (const int*)d_in[7];
    const int*   rout   = (const int*)d_in[8];
    int n = in_sizes[0] / 16;

    float *acc1, *acc2;
    cudaGetSymbolAddress((void**)&acc1, g_acc1);
    cudaGetSymbolAddress((void**)&acc2, g_acc2);

    int tiles = (n + TILE - 1) / TILE;
    int segthreads = KOFF * (tiles + 1);

    seg_k<<<(segthreads + 255) / 256, 256>>>(rout, n, tiles);

    conv_k<16, false><<<tiles, 256>>>(feats, W1, rin, rout, acc1, n, 0);
    finalize_k<<<1, 32>>>(gamma1, beta1, n, 0, 128);

    conv_k<32, true><<<tiles, 256>>>(acc1, W2, rin, rout, acc2, n, 64);
    finalize_k<<<1, 32>>>(gamma2, beta2, n, 64, 192);

    apply_k<<<1184, 256>>>(acc2, (float*)d_out, n, 192);
}

// round 3
// speedup vs baseline: 2.0329x; 1.0225x over previous
#include <cuda_runtime.h>

#define NMAX 200000
#define KOFF 27
#define TILE 128
#define TILESMAX ((NMAX + TILE - 1) / TILE)
#define SEGW (TILESMAX + 1)
#define BN_EPS 1e-3f

// ---------------- scratch (__device__ globals; no allocs allowed) ----------
__device__ __align__(256) float g_acc1[(size_t)NMAX * 32];
__device__ __align__(256) float g_acc2[(size_t)NMAX * 32];
__device__ int   g_seg[KOFF * SEGW];
// [0:64) layer1 sum/sumsq  [64:128) layer2 sum/sumsq
// [128:192) layer1 scale/shift  [192:256) layer2 scale/shift
__device__ float g_sums[256];

// ---------------- seg: per (k, dst-tile) pair-range via binary search ------
// rule_out[k] is sorted ascending (padding value n at the tail).
__global__ void seg_k(const int* __restrict__ rout, int n, int tiles) {
    if (blockIdx.x == 0 && threadIdx.x < 128) g_sums[threadIdx.x] = 0.f;
    int idx = blockIdx.x * blockDim.x + threadIdx.x;
    int total = KOFF * (tiles + 1);
    if (idx >= total) return;
    int k = idx / (tiles + 1), t = idx % (tiles + 1);
    int target = t * TILE;
    if (target > n) target = n;           // clamp: padding rows hold value n
    const int* a = rout + (size_t)k * n;
    int lo = 0, hi = n;
    while (lo < hi) {
        int mid = (lo + hi) >> 1;
        if (a[mid] < target) lo = mid + 1; else hi = mid;
    }
    g_seg[k * SEGW + t] = lo;
}

// ---------------- conv: dst-tile smem accumulation, ci-vectorized GEMM -----
// Block owns 128 output rows. For each offset k, pairs hitting this tile are
// the contiguous range [seg[k][t], seg[k][t+1]). Gather -> register-tile GEMM
// with float4 A/W reads over the K dim -> smem C scatter-add -> single store
// + fused BN-stats reduction.
template <int CIN, bool BNIN>
__global__ void __launch_bounds__(256) conv_k(
    const float* __restrict__ X, const float* __restrict__ W,
    const int* __restrict__ rin, const int* __restrict__ rout,
    float* __restrict__ out, int n, int statoff)
{
    const int AS = CIN + 4;               // Ash row stride in floats (16B mult, bank-spread)
    const int CH = CIN / 4;               // float4 chunks per feature row (4 or 8)
    const int CSH = (CIN == 32) ? 3 : 2;  // log2(CH)
    __shared__ float C[128 * 36];         // C tile, stride 36 floats
    __shared__ float Ash[128 * (CIN + 4)];
    __shared__ float Wsh[CIN * 32];
    __shared__ int   dsh[128];
    __shared__ int   ssh[KOFF + 1];       // seg boundaries for this tile
    __shared__ float red[512];
    __shared__ float bns[64];             // input-BN scale/shift (conv2)

    int tx = threadIdx.x;
    int tile = blockIdx.x;
    int r0 = tile * TILE;

    if (BNIN && tx < 64) bns[tx] = g_sums[128 + tx];
    if (tx < KOFF) ssh[tx] = g_seg[tx * SEGW + tile];
    if (tx == KOFF) ssh[0 + KOFF] = 0;    // placeholder; ends loaded below
    __shared__ int esh[KOFF];
    if (tx < KOFF) esh[tx] = g_seg[tx * SEGW + tile + 1];
    for (int i = tx; i < 128 * 36; i += 256) C[i] = 0.f;
    __syncthreads();

    const int rg = tx >> 3, cg = tx & 7;
    const int rb = rg * 4;

    for (int k = 0; k < KOFF; k++) {
        int s = ssh[k];
        int L = esh[k] - s;
        if (L == 0) continue;             // uniform across block: safe

        __syncthreads();                  // prev-iter compute done before restage

        // stage W_k (float4)
        const float4* Wk4 = (const float4*)(W + (size_t)k * CIN * 32);
        #pragma unroll
        for (int i = tx; i < CIN * 8; i += 256) ((float4*)Wsh)[i] = Wk4[i];

        if (tx < L) dsh[tx] = __ldg(rout + (size_t)k * n + s + tx) - r0;
        for (int i = tx; i < L * CH; i += 256) {
            int row = i >> CSH, co = i & (CH - 1);
            int src = __ldg(rin + (size_t)k * n + s + row);
            float4 v = ((const float4*)(X + (size_t)src * CIN))[co];
            if (BNIN) {
                float4 sc = *(const float4*)&bns[co * 4];
                float4 sh = *(const float4*)&bns[32 + co * 4];
                v.x = fmaxf(fmaf(v.x, sc.x, sh.x), 0.f);
                v.y = fmaxf(fmaf(v.y, sc.y, sh.y), 0.f);
                v.z = fmaxf(fmaf(v.z, sc.z, sh.z), 0.f);
                v.w = fmaxf(fmaf(v.w, sc.w, sh.w), 0.f);
            }
            *(float4*)&Ash[row * AS + co * 4] = v;
        }
        __syncthreads();

        if (rb < L) {
            float4 cc[4];
            #pragma unroll
            for (int i = 0; i < 4; i++) cc[i] = make_float4(0.f, 0.f, 0.f, 0.f);

            #pragma unroll
            for (int c4 = 0; c4 < CIN / 4; c4++) {
                int ci = c4 * 4;
                // A: 4 rows x 4 consecutive ci (conflict-free: row stride AS)
                float4 a0 = *(const float4*)&Ash[(rb + 0) * AS + ci];
                float4 a1 = *(const float4*)&Ash[(rb + 1) * AS + ci];
                float4 a2 = *(const float4*)&Ash[(rb + 2) * AS + ci];
                float4 a3 = *(const float4*)&Ash[(rb + 3) * AS + ci];
                // W: 4 ci rows for this thread's 4 output cols
                float4 w0 = *(const float4*)&Wsh[(ci + 0) * 32 + cg * 4];
                float4 w1 = *(const float4*)&Wsh[(ci + 1) * 32 + cg * 4];
                float4 w2 = *(const float4*)&Wsh[(ci + 2) * 32 + cg * 4];
                float4 w3 = *(const float4*)&Wsh[(ci + 3) * 32 + cg * 4];

                cc[0].x = fmaf(a0.x, w0.x, cc[0].x); cc[0].y = fmaf(a0.x, w0.y, cc[0].y);
                cc[0].z = fmaf(a0.x, w0.z, cc[0].z); cc[0].w = fmaf(a0.x, w0.w, cc[0].w);
                cc[1].x = fmaf(a1.x, w0.x, cc[1].x); cc[1].y = fmaf(a1.x, w0.y, cc[1].y);
                cc[1].z = fmaf(a1.x, w0.z, cc[1].z); cc[1].w = fmaf(a1.x, w0.w, cc[1].w);
                cc[2].x = fmaf(a2.x, w0.x, cc[2].x); cc[2].y = fmaf(a2.x, w0.y, cc[2].y);
                cc[2].z = fmaf(a2.x, w0.z, cc[2].z); cc[2].w = fmaf(a2.x, w0.w, cc[2].w);
                cc[3].x = fmaf(a3.x, w0.x, cc[3].x); cc[3].y = fmaf(a3.x, w0.y, cc[3].y);
                cc[3].z = fmaf(a3.x, w0.z, cc[3].z); cc[3].w = fmaf(a3.x, w0.w, cc[3].w);

                cc[0].x = fmaf(a0.y, w1.x, cc[0].x); cc[0].y = fmaf(a0.y, w1.y, cc[0].y);
                cc[0].z = fmaf(a0.y, w1.z, cc[0].z); cc[0].w = fmaf(a0.y, w1.w, cc[0].w);
                cc[1].x = fmaf(a1.y, w1.x, cc[1].x); cc[1].y = fmaf(a1.y, w1.y, cc[1].y);
                cc[1].z = fmaf(a1.y, w1.z, cc[1].z); cc[1].w = fmaf(a1.y, w1.w, cc[1].w);
                cc[2].x = fmaf(a2.y, w1.x, cc[2].x); cc[2].y = fmaf(a2.y, w1.y, cc[2].y);
                cc[2].z = fmaf(a2.y, w1.z, cc[2].z); cc[2].w = fmaf(a2.y, w1.w, cc[2].w);
                cc[3].x = fmaf(a3.y, w1.x, cc[3].x); cc[3].y = fmaf(a3.y, w1.y, cc[3].y);
                cc[3].z = fmaf(a3.y, w1.z, cc[3].z); cc[3].w = fmaf(a3.y, w1.w, cc[3].w);

                cc[0].x = fmaf(a0.z, w2.x, cc[0].x); cc[0].y = fmaf(a0.z, w2.y, cc[0].y);
                cc[0].z = fmaf(a0.z, w2.z, cc[0].z); cc[0].w = fmaf(a0.z, w2.w, cc[0].w);
                cc[1].x = fmaf(a1.z, w2.x, cc[1].x); cc[1].y = fmaf(a1.z, w2.y, cc[1].y);
                cc[1].z = fmaf(a1.z, w2.z, cc[1].z); cc[1].w = fmaf(a1.z, w2.w, cc[1].w);
                cc[2].x = fmaf(a2.z, w2.x, cc[2].x); cc[2].y = fmaf(a2.z, w2.y, cc[2].y);
                cc[2].z = fmaf(a2.z, w2.z, cc[2].z); cc[2].w = fmaf(a2.z, w2.w, cc[2].w);
                cc[3].x = fmaf(a3.z, w2.x, cc[3].x); cc[3].y = fmaf(a3.z, w2.y, cc[3].y);
                cc[3].z = fmaf(a3.z, w2.z, cc[3].z); cc[3].w = fmaf(a3.z, w2.w, cc[3].w);

                cc[0].x = fmaf(a0.w, w3.x, cc[0].x); cc[0].y = fmaf(a0.w, w3.y, cc[0].y);
                cc[0].z = fmaf(a0.w, w3.z, cc[0].z); cc[0].w = fmaf(a0.w, w3.w, cc[0].w);
                cc[1].x = fmaf(a1.w, w3.x, cc[1].x); cc[1].y = fmaf(a1.w, w3.y, cc[1].y);
                cc[1].z = fmaf(a1.w, w3.z, cc[1].z); cc[1].w = fmaf(a1.w, w3.w, cc[1].w);
                cc[2].x = fmaf(a2.w, w3.x, cc[2].x); cc[2].y = fmaf(a2.w, w3.y, cc[2].y);
                cc[2].z = fmaf(a2.w, w3.z, cc[2].z); cc[2].w = fmaf(a2.w, w3.w, cc[2].w);
                cc[3].x = fmaf(a3.w, w3.x, cc[3].x); cc[3].y = fmaf(a3.w, w3.y, cc[3].y);
                cc[3].z = fmaf(a3.w, w3.z, cc[3].z); cc[3].w = fmaf(a3.w, w3.w, cc[3].w);
            }

            #pragma unroll
            for (int i = 0; i < 4; i++) {
                int row = rb + i;
                if (row < L) {
                    // distinct (dst, cg) per lane within an offset: race-free
                    float* p = &C[dsh[row] * 36 + cg * 4];
                    float4 cv = *(float4*)p;
                    cv.x += cc[i].x; cv.y += cc[i].y;
                    cv.z += cc[i].z; cv.w += cc[i].w;
                    *(float4*)p = cv;
                }
            }
        }
    }
    __syncthreads();

    // epilogue: store C tile once + fused BN statistics
    int nrows = n - r0; if (nrows > 128) nrows = 128;
    for (int i = tx; i < nrows * 8; i += 256) {
        int row = i >> 3, co = i & 7;
        ((float4*)(out + (size_t)(r0 + row) * 32))[co] = *(float4*)&C[row * 36 + co * 4];
    }
    int ch = tx & 31, rb2 = tx >> 5;
    float s = 0.f, q = 0.f;
    for (int r = rb2; r < nrows; r += 8) {
        float v = C[r * 36 + ch];
        s += v;
        q = fmaf(v, v, q);
    }
    red[tx] = s; red[256 + tx] = q;
    __syncthreads();
    if (tx < 32) {
        float S = 0.f, Q = 0.f;
        #pragma unroll
        for (int w = 0; w < 8; w++) { S += red[w * 32 + tx]; Q += red[256 + w * 32 + tx]; }
        atomicAdd(&g_sums[statoff + tx], S);
        atomicAdd(&g_sums[statoff + 32 + tx], Q);
    }
}

// ---------------- BN finalize: per-channel scale/shift ---------------------
__global__ void finalize_k(const float* __restrict__ gamma,
                           const float* __restrict__ beta,
                           int n, int off, int outoff) {
    int c = threadIdx.x;
    float inv_n = 1.f / (float)n;
    float mu  = g_sums[off + c] * inv_n;
    float var = g_sums[off + 32 + c] * inv_n - mu * mu;
    float sc  = gamma[c] * rsqrtf(var + BN_EPS);
    g_sums[outoff + c] = sc;
    g_sums[outoff + 32 + c] = beta[c] - mu * sc;
}

// ---------------- BN apply + ReLU (final output only) ----------------------
__global__ void apply_k(const float* __restrict__ in, float* __restrict__ out,
                        int n, int soff) {
    int total = n * 8;
    for (int i = blockIdx.x * blockDim.x + threadIdx.x; i < total;
         i += gridDim.x * blockDim.x) {
        int c4 = (i & 7) * 4;
        float4 v  = ((const float4*)in)[i];
        float4 sc = *(const float4*)&g_sums[soff + c4];
        float4 sh = *(const float4*)&g_sums[soff + 32 + c4];
        float4 o;
        o.x = fmaxf(fmaf(v.x, sc.x, sh.x), 0.f);
        o.y = fmaxf(fmaf(v.y, sc.y, sh.y), 0.f);
        o.z = fmaxf(fmaf(v.z, sc.z, sh.z), 0.f);
        o.w = fmaxf(fmaf(v.w, sc.w, sh.w), 0.f);
        ((float4*)out)[i] = o;
    }
}

// ---------------- launch ---------------------------------------------------
extern "C" void kernel_launch(void* const* d_in, const int* in_sizes, int n_in,
                              void* d_out, int out_size) {
    const float* feats  = (const float*)d_in[0];
    const float* W1     = (const float*)d_in[1];
    const float* gamma1 = (const float*)d_in[2];
    const float* beta1  = (const float*)d_in[3];
    const float* W2     = (const float*)d_in[4];
    const float* gamma2 = (const float*)d_in[5];
    const float* beta2  = (const float*)d_in[6];
    const int*   rin    = (const int*)d_in[7];
    const int*   rout   = (const int*)d_in[8];
    int n = in_sizes[0] / 16;

    float *acc1, *acc2;
    cudaGetSymbolAddress((void**)&acc1, g_acc1);
    cudaGetSymbolAddress((void**)&acc2, g_acc2);

    int tiles = (n + TILE - 1) / TILE;
    int segthreads = KOFF * (tiles + 1);

    seg_k<<<(segthreads + 255) / 256, 256>>>(rout, n, tiles);

    conv_k<16, false><<<tiles, 256>>>(feats, W1, rin, rout, acc1, n, 0);
    finalize_k<<<1, 32>>>(gamma1, beta1, n, 0, 128);

    conv_k<32, true><<<tiles, 256>>>(acc1, W2, rin, rout, acc2, n, 64);
    finalize_k<<<1, 32>>>(gamma2, beta2, n, 64, 192);

    apply_k<<<1184, 256>>>(acc2, (float*)d_out, n, 192);
}

// round 4
// speedup vs baseline: 2.1176x; 1.0417x over previous
#include <cuda_runtime.h>

#define NMAX 200000
#define KOFF 27
#define TILE 128
#define TILESMAX ((NMAX + TILE - 1) / TILE)
#define SEGW (TILESMAX + 1)
#define BN_EPS 1e-3f

// ---------------- scratch (__device__ globals; no allocs allowed) ----------
__device__ __align__(256) float g_acc1[(size_t)NMAX * 32];
__device__ __align__(256) float g_acc2[(size_t)NMAX * 32];
__device__ int   g_seg[KOFF * SEGW];
// [0:64) layer1 sum/sumsq  [64:128) layer2 sum/sumsq
// [128:192) layer1 scale/shift  [192:256) layer2 scale/shift
__device__ float g_sums[256];

// ---------------- seg: per (k, dst-tile) pair-range via binary search ------
__global__ void seg_k(const int* __restrict__ rout, int n, int tiles) {
    if (blockIdx.x == 0 && threadIdx.x < 128) g_sums[threadIdx.x] = 0.f;
    int idx = blockIdx.x * blockDim.x + threadIdx.x;
    int total = KOFF * (tiles + 1);
    if (idx >= total) return;
    int k = idx / (tiles + 1), t = idx % (tiles + 1);
    int target = t * TILE;
    if (target > n) target = n;
    const int* a = rout + (size_t)k * n;
    int lo = 0, hi = n;
    while (lo < hi) {
        int mid = (lo + hi) >> 1;
        if (a[mid] < target) lo = mid + 1; else hi = mid;
    }
    g_seg[k * SEGW + t] = lo;
}

// ---------------- conv: pipelined gather + dst-tile smem accumulation ------
// Per offset: store prefetched regs -> smem[buf]; ONE barrier; prefetch next
// offset's gather into regs (latency hidden under compute); compute.
template <int CIN, bool BNIN>
__global__ void __launch_bounds__(256) conv_k(
    const float* __restrict__ X, const float* __restrict__ W,
    const int* __restrict__ rin, const int* __restrict__ rout,
    float* __restrict__ out, int n, int statoff)
{
    const int AS  = CIN + 4;              // Ash row stride (floats)
    const int CH  = CIN / 4;              // float4 per feature row
    const int CSH = (CIN == 32) ? 3 : 2;  // log2(CH)
    const int PF  = CH / 2;               // prefetch float4s per thread
    const int WF4 = CIN * 8;              // float4 count of one W_k

    extern __shared__ float smem[];
    float* C    = smem;                            // 128*36
    float* AshB = C + 128 * 36;                    // 2 * 128*AS
    float* WshB = AshB + 2 * 128 * AS;             // 2 * CIN*32
    float* red  = WshB + 2 * CIN * 32;             // 512
    float* bns  = red + 512;                       // 64
    int*   dshB = (int*)(bns + 64);                // 2 * 128
    int*   klist = dshB + 256;                     // 27
    int*   klo   = klist + KOFF;                   // 27
    int*   kln   = klo + KOFF;                     // 27
    int*   sst   = kln + KOFF;                     // 27
    int*   sen   = sst + KOFF;                     // 27
    int*   nk_sh = sen + KOFF;                     // 1

    int tx = threadIdx.x;
    int tile = blockIdx.x;
    int r0 = tile * TILE;

    if (BNIN && tx < 64) bns[tx] = g_sums[128 + tx];
    if (tx < KOFF) { sst[tx] = g_seg[tx * SEGW + tile]; sen[tx] = g_seg[tx * SEGW + tile + 1]; }
    for (int i = tx; i < 128 * 36; i += 256) C[i] = 0.f;
    __syncthreads();
    if (tx == 0) {
        int m = 0;
        for (int k = 0; k < KOFF; k++) {
            int L = sen[k] - sst[k];
            if (L > 0) { klist[m] = k; klo[m] = sst[k]; kln[m] = L; m++; }
        }
        *nk_sh = m;
    }
    __syncthreads();
    int nk = *nk_sh;

    float4 pv[PF];
    float4 pw = make_float4(0.f, 0.f, 0.f, 0.f);
    int pdst = 0;
    int curL = 0;

    auto prefetch = [&](int j) {
        int k = klist[j], s = klo[j], L = kln[j];
        curL = L;
        const float4* Wk4 = (const float4*)(W + (size_t)k * CIN * 32);
        if (tx < WF4) pw = Wk4[tx];
        if (tx < L) pdst = __ldg(rout + (size_t)k * n + s + tx);
        #pragma unroll
        for (int i = 0; i < PF; i++) {
            int gi = tx + i * 256;
            int row = gi >> CSH, co = gi & (CH - 1);
            if (row < L) {
                int src = __ldg(rin + (size_t)k * n + s + row);
                float4 v = ((const float4*)(X + (size_t)src * CIN))[co];
                if (BNIN) {
                    float4 sc = *(const float4*)&bns[co * 4];
                    float4 sh = *(const float4*)&bns[32 + co * 4];
                    v.x = fmaxf(fmaf(v.x, sc.x, sh.x), 0.f);
                    v.y = fmaxf(fmaf(v.y, sc.y, sh.y), 0.f);
                    v.z = fmaxf(fmaf(v.z, sc.z, sh.z), 0.f);
                    v.w = fmaxf(fmaf(v.w, sc.w, sh.w), 0.f);
                }
                pv[i] = v;
            }
        }
    };

    if (nk > 0) prefetch(0);

    const int rg = tx >> 3, cg = tx & 7;
    const int rb = rg * 4;

    for (int idx = 0; idx < nk; idx++) {
        int buf = idx & 1;
        int L = curL;
        float* Ash = AshB + buf * 128 * AS;
        float* Wsh = WshB + buf * CIN * 32;
        int*   dsh = dshB + buf * 128;

        // store staged regs into this buffer (last read at idx-2, sealed by
        // idx-1's barrier)
        if (tx < WF4) ((float4*)Wsh)[tx] = pw;
        if (tx < L) dsh[tx] = pdst - r0;
        #pragma unroll
        for (int i = 0; i < PF; i++) {
            int gi = tx + i * 256;
            int row = gi >> CSH, co = gi & (CH - 1);
            if (row < L) *(float4*)&Ash[row * AS + co * 4] = pv[i];
        }
        __syncthreads();

        if (idx + 1 < nk) prefetch(idx + 1);   // hidden under compute below

        if (rb < L) {
            float4 cc[4];
            #pragma unroll
            for (int i = 0; i < 4; i++) cc[i] = make_float4(0.f, 0.f, 0.f, 0.f);

            #pragma unroll
            for (int c4 = 0; c4 < CIN / 4; c4++) {
                int ci = c4 * 4;
                float4 a0 = *(const float4*)&Ash[(rb + 0) * AS + ci];
                float4 a1 = *(const float4*)&Ash[(rb + 1) * AS + ci];
                float4 a2 = *(const float4*)&Ash[(rb + 2) * AS + ci];
                float4 a3 = *(const float4*)&Ash[(rb + 3) * AS + ci];
                float4 w0 = *(const float4*)&Wsh[(ci + 0) * 32 + cg * 4];
                float4 w1 = *(const float4*)&Wsh[(ci + 1) * 32 + cg * 4];
                float4 w2 = *(const float4*)&Wsh[(ci + 2) * 32 + cg * 4];
                float4 w3 = *(const float4*)&Wsh[(ci + 3) * 32 + cg * 4];

                cc[0].x = fmaf(a0.x, w0.x, cc[0].x); cc[0].y = fmaf(a0.x, w0.y, cc[0].y);
                cc[0].z = fmaf(a0.x, w0.z, cc[0].z); cc[0].w = fmaf(a0.x, w0.w, cc[0].w);
                cc[1].x = fmaf(a1.x, w0.x, cc[1].x); cc[1].y = fmaf(a1.x, w0.y, cc[1].y);
                cc[1].z = fmaf(a1.x, w0.z, cc[1].z); cc[1].w = fmaf(a1.x, w0.w, cc[1].w);
                cc[2].x = fmaf(a2.x, w0.x, cc[2].x); cc[2].y = fmaf(a2.x, w0.y, cc[2].y);
                cc[2].z = fmaf(a2.x, w0.z, cc[2].z); cc[2].w = fmaf(a2.x, w0.w, cc[2].w);
                cc[3].x = fmaf(a3.x, w0.x, cc[3].x); cc[3].y = fmaf(a3.x, w0.y, cc[3].y);
                cc[3].z = fmaf(a3.x, w0.z, cc[3].z); cc[3].w = fmaf(a3.x, w0.w, cc[3].w);

                cc[0].x = fmaf(a0.y, w1.x, cc[0].x); cc[0].y = fmaf(a0.y, w1.y, cc[0].y);
                cc[0].z = fmaf(a0.y, w1.z, cc[0].z); cc[0].w = fmaf(a0.y, w1.w, cc[0].w);
                cc[1].x = fmaf(a1.y, w1.x, cc[1].x); cc[1].y = fmaf(a1.y, w1.y, cc[1].y);
                cc[1].z = fmaf(a1.y, w1.z, cc[1].z); cc[1].w = fmaf(a1.y, w1.w, cc[1].w);
                cc[2].x = fmaf(a2.y, w1.x, cc[2].x); cc[2].y = fmaf(a2.y, w1.y, cc[2].y);
                cc[2].z = fmaf(a2.y, w1.z, cc[2].z); cc[2].w = fmaf(a2.y, w1.w, cc[2].w);
                cc[3].x = fmaf(a3.y, w1.x, cc[3].x); cc[3].y = fmaf(a3.y, w1.y, cc[3].y);
                cc[3].z = fmaf(a3.y, w1.z, cc[3].z); cc[3].w = fmaf(a3.y, w1.w, cc[3].w);

                cc[0].x = fmaf(a0.z, w2.x, cc[0].x); cc[0].y = fmaf(a0.z, w2.y, cc[0].y);
                cc[0].z = fmaf(a0.z, w2.z, cc[0].z); cc[0].w = fmaf(a0.z, w2.w, cc[0].w);
                cc[1].x = fmaf(a1.z, w2.x, cc[1].x); cc[1].y = fmaf(a1.z, w2.y, cc[1].y);
                cc[1].z = fmaf(a1.z, w2.z, cc[1].z); cc[1].w = fmaf(a1.z, w2.w, cc[1].w);
                cc[2].x = fmaf(a2.z, w2.x, cc[2].x); cc[2].y = fmaf(a2.z, w2.y, cc[2].y);
                cc[2].z = fmaf(a2.z, w2.z, cc[2].z); cc[2].w = fmaf(a2.z, w2.w, cc[2].w);
                cc[3].x = fmaf(a3.z, w2.x, cc[3].x); cc[3].y = fmaf(a3.z, w2.y, cc[3].y);
                cc[3].z = fmaf(a3.z, w2.z, cc[3].z); cc[3].w = fmaf(a3.z, w2.w, cc[3].w);

                cc[0].x = fmaf(a0.w, w3.x, cc[0].x); cc[0].y = fmaf(a0.w, w3.y, cc[0].y);
                cc[0].z = fmaf(a0.w, w3.z, cc[0].z); cc[0].w = fmaf(a0.w, w3.w, cc[0].w);
                cc[1].x = fmaf(a1.w, w3.x, cc[1].x); cc[1].y = fmaf(a1.w, w3.y, cc[1].y);
                cc[1].z = fmaf(a1.w, w3.z, cc[1].z); cc[1].w = fmaf(a1.w, w3.w, cc[1].w);
                cc[2].x = fmaf(a2.w, w3.x, cc[2].x); cc[2].y = fmaf(a2.w, w3.y, cc[2].y);
                cc[2].z = fmaf(a2.w, w3.z, cc[2].z); cc[2].w = fmaf(a2.w, w3.w, cc[2].w);
                cc[3].x = fmaf(a3.w, w3.x, cc[3].x); cc[3].y = fmaf(a3.w, w3.y, cc[3].y);
                cc[3].z = fmaf(a3.w, w3.z, cc[3].z); cc[3].w = fmaf(a3.w, w3.w, cc[3].w);
            }

            #pragma unroll
            for (int i = 0; i < 4; i++) {
                int row = rb + i;
                if (row < L) {
                    float* p = &C[dsh[row] * 36 + cg * 4];
                    float4 cv = *(float4*)p;
                    cv.x += cc[i].x; cv.y += cc[i].y;
                    cv.z += cc[i].z; cv.w += cc[i].w;
                    *(float4*)p = cv;
                }
            }
        }
    }
    __syncthreads();

    // epilogue: store C tile once + fused BN statistics
    int nrows = n - r0; if (nrows > 128) nrows = 128;
    for (int i = tx; i < nrows * 8; i += 256) {
        int row = i >> 3, co = i & 7;
        ((float4*)(out + (size_t)(r0 + row) * 32))[co] = *(float4*)&C[row * 36 + co * 4];
    }
    int ch = tx & 31, rb2 = tx >> 5;
    float s = 0.f, q = 0.f;
    for (int r = rb2; r < nrows; r += 8) {
        float v = C[r * 36 + ch];
        s += v;
        q = fmaf(v, v, q);
    }
    red[tx] = s; red[256 + tx] = q;
    __syncthreads();
    if (tx < 32) {
        float S = 0.f, Q = 0.f;
        #pragma unroll
        for (int w = 0; w < 8; w++) { S += red[w * 32 + tx]; Q += red[256 + w * 32 + tx]; }
        atomicAdd(&g_sums[statoff + tx], S);
        atomicAdd(&g_sums[statoff + 32 + tx], Q);
    }
}

// ---------------- BN finalize ---------------------------------------------
__global__ void finalize_k(const float* __restrict__ gamma,
                           const float* __restrict__ beta,
                           int n, int off, int outoff) {
    int c = threadIdx.x;
    float inv_n = 1.f / (float)n;
    float mu  = g_sums[off + c] * inv_n;
    float var = g_sums[off + 32 + c] * inv_n - mu * mu;
    float sc  = gamma[c] * rsqrtf(var + BN_EPS);
    g_sums[outoff + c] = sc;
    g_sums[outoff + 32 + c] = beta[c] - mu * sc;
}

// ---------------- BN apply + ReLU (final output only) ----------------------
__global__ void apply_k(const float* __restrict__ in, float* __restrict__ out,
                        int n, int soff) {
    int total = n * 8;
    for (int i = blockIdx.x * blockDim.x + threadIdx.x; i < total;
         i += gridDim.x * blockDim.x) {
        int c4 = (i & 7) * 4;
        float4 v  = ((const float4*)in)[i];
        float4 sc = *(const float4*)&g_sums[soff + c4];
        float4 sh = *(const float4*)&g_sums[soff + 32 + c4];
        float4 o;
        o.x = fmaxf(fmaf(v.x, sc.x, sh.x), 0.f);
        o.y = fmaxf(fmaf(v.y, sc.y, sh.y), 0.f);
        o.z = fmaxf(fmaf(v.z, sc.z, sh.z), 0.f);
        o.w = fmaxf(fmaf(v.w, sc.w, sh.w), 0.f);
        ((float4*)out)[i] = o;
    }
}

// ---------------- launch ---------------------------------------------------
template <int CIN>
static int conv_smem_bytes() {
    int fl = 128 * 36 + 2 * 128 * (CIN + 4) + 2 * CIN * 32 + 512 + 64;
    int in = 2 * 128 + KOFF * 5 + 1;
    return (fl + in) * 4 + 16;
}

extern "C" void kernel_launch(void* const* d_in, const int* in_sizes, int n_in,
                              void* d_out, int out_size) {
    const float* feats  = (const float*)d_in[0];
    const float* W1     = (const float*)d_in[1];
    const float* gamma1 = (const float*)d_in[2];
    const float* beta1  = (const float*)d_in[3];
    const float* W2     = (const float*)d_in[4];
    const float* gamma2 = (const float*)d_in[5];
    const float* beta2  = (const float*)d_in[6];
    const int*   rin    = (const int*)d_in[7];
    const int*   rout   = (const int*)d_in[8];
    int n = in_sizes[0] / 16;

    float *acc1, *acc2;
    cudaGetSymbolAddress((void**)&acc1, g_acc1);
    cudaGetSymbolAddress((void**)&acc2, g_acc2);

    int smem1 = conv_smem_bytes<16>();
    int smem2 = conv_smem_bytes<32>();
    cudaFuncSetAttribute(conv_k<16, false>, cudaFuncAttributeMaxDynamicSharedMemorySize, smem1);
    cudaFuncSetAttribute(conv_k<32, true>,  cudaFuncAttributeMaxDynamicSharedMemorySize, smem2);

    int tiles = (n + TILE - 1) / TILE;
    int segthreads = KOFF * (tiles + 1);

    seg_k<<<(segthreads + 255) / 256, 256>>>(rout, n, tiles);

    conv_k<16, false><<<tiles, 256, smem1>>>(feats, W1, rin, rout, acc1, n, 0);
    finalize_k<<<1, 32>>>(gamma1, beta1, n, 0, 128);

    conv_k<32, true><<<tiles, 256, smem2>>>(acc1, W2, rin, rout, acc2, n, 64);
    finalize_k<<<1, 32>>>(gamma2, beta2, n, 64, 192);

    apply_k<<<1184, 256>>>(acc2, (float*)d_out, n, 192);
}